// round 15
// baseline (speedup 1.0000x reference)
#include <cuda_runtime.h>
#include <cuda_bf16.h>

// Fixed shapes
#define M_ROWS   2048
#define N_LAT    8192
#define DIM      256
#define ROWS_CTA 16
#define LATS_CTA 256
#define NRB      (M_ROWS / ROWS_CTA)   // 128
#define NLB      (N_LAT / LATS_CTA)    // 32
#define NQ_TOT   (DIM / 4)             // 64 quads
#define NSTAGE   16                    // stages of 16 floats (4 quads)
#define QPS      4
#define STAGE_BYTES (QPS * LATS_CTA * 16)   // 16KB

#define ROWS_BYTES (NQ_TOT * ROWS_CTA * 16)      // 16KB
#define LATS_BYTES (2 * QPS * LATS_CTA * 16)     // 32KB
#define K1_SMEM    (ROWS_BYTES + LATS_BYTES + 64)

typedef unsigned long long ull;

__device__ float4 g_latT[NQ_TOT * N_LAT];   // quad-major transposed latents (8MB)
__device__ float  g_cand[M_ROWS * NLB * 4];
__device__ float  g_tail[M_ROWS];

// A += |R + L|  (packed f32x2; R holds negated row values)
#define ABSACC(A, R, L) do { ull _d;                                \
    asm("add.rn.f32x2 %0, %1, %2;" : "=l"(_d) : "l"(R), "l"(L));    \
    _d &= 0x7fffffff7fffffffULL;                                    \
    asm("add.rn.f32x2 %0, %1, %2;" : "=l"(A) : "l"(A), "l"(_d));    \
} while (0)

#define MBAR_INIT(a, c) \
    asm volatile("mbarrier.init.shared.b64 [%0], %1;" :: "r"(a), "r"(c) : "memory")
#define MBAR_EXPECT(a, b) \
    asm volatile("mbarrier.arrive.expect_tx.shared.b64 _, [%0], %1;" :: "r"(a), "r"(b) : "memory")
#define BULK_G2S(dst, src, n, bar) \
    asm volatile("cp.async.bulk.shared::cluster.global.mbarrier::complete_tx::bytes [%0], [%1], %2, [%3];" \
                 :: "r"(dst), "l"(src), "r"(n), "r"(bar) : "memory")

static __device__ __forceinline__ void mbar_wait(unsigned bar, unsigned parity) {
    asm volatile(
        "{\n\t"
        ".reg .pred P;\n\t"
        "WAIT_%=:\n\t"
        "mbarrier.try_wait.parity.acquire.cta.shared::cta.b64 P, [%0], %1, 0x989680;\n\t"
        "@P bra.uni DONE_%=;\n\t"
        "bra.uni WAIT_%=;\n\t"
        "DONE_%=:\n\t"
        "}" :: "r"(bar), "r"(parity) : "memory");
}

static __device__ __forceinline__ void ins4(float v, float& m0, float& m1, float& m2, float& m3) {
    if (v < m3) {
        float c2 = fminf(v,  m2), d3 = fmaxf(v,  m2);
        float c1 = fminf(c2, m1), d2 = fmaxf(c2, m1);
        float c0 = fminf(c1, m0), d1 = fmaxf(c1, m0);
        m0 = c0; m1 = d1; m2 = d2; m3 = d3;
    }
}

static __device__ __forceinline__ float huber1(float x) {
    return (x < 1.0f) ? (0.5f * x * x) : (x - 0.5f);
}

// ---------------------------------------------------------------------------
// Kernel 0: transpose latents -> g_latT[quad][lat] (float4 of 4 consecutive d)
// ---------------------------------------------------------------------------
__global__ void k0_transpose(const float* __restrict__ lat) {
    __shared__ float4 sm[32][65];   // padded
    const int tid = threadIdx.x;
    const int lb = blockIdx.x * 32;
    #pragma unroll
    for (int k = 0; k < 8; ++k) {
        int idx = tid + k * 256;      // 2048 float4
        int r = idx >> 6, q = idx & 63;
        sm[r][q] = reinterpret_cast<const float4*>(lat)[(size_t)(lb + r) * 64 + q];
    }
    __syncthreads();
    #pragma unroll
    for (int k = 0; k < 8; ++k) {
        int idx = tid + k * 256;
        int q = idx >> 5, l = idx & 31;
        g_latT[(size_t)q * N_LAT + lb + l] = sm[l][q];
    }
}

// ---------------------------------------------------------------------------
// Kernel 1: L1 cdist 16-row x 256-latent tile; min-4 per (row, latblock)
// grid (128, 32), block 256, 3 CTAs/SM, 48KB dynamic smem.
// Double-buffered cp.async.bulk staging (no LDGSTS issue tax).
// ---------------------------------------------------------------------------
__global__ void __launch_bounds__(256, 3)
k1_cdist_min4(const float* __restrict__ space) {
    extern __shared__ char smem[];
    float4* rowS = reinterpret_cast<float4*>(smem);                 // [64][16]
    float4* latS = reinterpret_cast<float4*>(smem + ROWS_BYTES);    // [2][4][256]
    ull*    mbar = reinterpret_cast<ull*>(smem + ROWS_BYTES + LATS_BYTES);

    const int tid = threadIdx.x;
    const int rowBase = blockIdx.x * ROWS_CTA;
    const int latBase = blockIdx.y * LATS_CTA;
    const int r0 = (tid >> 6) * 4;     // warp-uniform: 0,4,8,12
    const int c0 = tid & 63;           // lats c0, c0+64, c0+128, c0+192

    const unsigned bar0 = (unsigned)__cvta_generic_to_shared(&mbar[0]);
    const unsigned bar1 = (unsigned)__cvta_generic_to_shared(&mbar[1]);

    if (tid == 0) { MBAR_INIT(bar0, 1); MBAR_INIT(bar1, 1); }

    // ---- stage rows negated: unit u -> row u&15, quad u>>4 (conflict-free) ----
    #pragma unroll
    for (int k = 0; k < 4; ++k) {
        int u = tid + k * 256;
        int r = u & 15, q = u >> 4;
        float4 v = reinterpret_cast<const float4*>(space + (size_t)(rowBase + r) * DIM)[q];
        rowS[q * ROWS_CTA + r] = make_float4(-v.x, -v.y, -v.z, -v.w);
    }
    __syncthreads();   // mbar init + rowS visible

    // prologue: stage 0 -> buf 0
    if (tid == 0) {
        MBAR_EXPECT(bar0, STAGE_BYTES);
        unsigned d = (unsigned)__cvta_generic_to_shared(&latS[0]);
        #pragma unroll
        for (int j = 0; j < QPS; ++j)
            BULK_G2S(d + j * LATS_CTA * 16,
                     (const char*)(g_latT + (size_t)j * N_LAT + latBase),
                     LATS_CTA * 16, bar0);
    }

    ull acc[4][4];
    #pragma unroll
    for (int i = 0; i < 4; ++i)
        #pragma unroll
        for (int j = 0; j < 4; ++j) acc[i][j] = 0ULL;

    for (int s = 0; s < NSTAGE; ++s) {
        mbar_wait((s & 1) ? bar1 : bar0, (s >> 1) & 1);
        __syncthreads();   // all threads passed wait => done reading buf[(s+1)&1]

        if (s + 1 < NSTAGE && tid == 0) {
            unsigned nb = ((s + 1) & 1) ? bar1 : bar0;
            MBAR_EXPECT(nb, STAGE_BYTES);
            unsigned d = (unsigned)__cvta_generic_to_shared(&latS[(size_t)((s + 1) & 1) * QPS * LATS_CTA]);
            #pragma unroll
            for (int j = 0; j < QPS; ++j)
                BULK_G2S(d + j * LATS_CTA * 16,
                         (const char*)(g_latT + (size_t)(QPS * (s + 1) + j) * N_LAT + latBase),
                         LATS_CTA * 16, nb);
        }

        #pragma unroll
        for (int q = 0; q < QPS; ++q) {
            const float4* lb = latS + ((size_t)(s & 1) * QPS + q) * LATS_CTA;
            ulonglong2 lv0 = *reinterpret_cast<const ulonglong2*>(lb + c0);
            ulonglong2 lv1 = *reinterpret_cast<const ulonglong2*>(lb + c0 + 64);
            ulonglong2 lv2 = *reinterpret_cast<const ulonglong2*>(lb + c0 + 128);
            ulonglong2 lv3 = *reinterpret_cast<const ulonglong2*>(lb + c0 + 192);
            const float4* rb = rowS + (QPS * s + q) * ROWS_CTA + r0;
            ulonglong2 rva = *reinterpret_cast<const ulonglong2*>(rb + 0);
            ulonglong2 rvb = *reinterpret_cast<const ulonglong2*>(rb + 1);
            ulonglong2 rvc = *reinterpret_cast<const ulonglong2*>(rb + 2);
            ulonglong2 rvd = *reinterpret_cast<const ulonglong2*>(rb + 3);
            ABSACC(acc[0][0], rva.x, lv0.x); ABSACC(acc[0][0], rva.y, lv0.y);
            ABSACC(acc[0][1], rva.x, lv1.x); ABSACC(acc[0][1], rva.y, lv1.y);
            ABSACC(acc[0][2], rva.x, lv2.x); ABSACC(acc[0][2], rva.y, lv2.y);
            ABSACC(acc[0][3], rva.x, lv3.x); ABSACC(acc[0][3], rva.y, lv3.y);
            ABSACC(acc[1][0], rvb.x, lv0.x); ABSACC(acc[1][0], rvb.y, lv0.y);
            ABSACC(acc[1][1], rvb.x, lv1.x); ABSACC(acc[1][1], rvb.y, lv1.y);
            ABSACC(acc[1][2], rvb.x, lv2.x); ABSACC(acc[1][2], rvb.y, lv2.y);
            ABSACC(acc[1][3], rvb.x, lv3.x); ABSACC(acc[1][3], rvb.y, lv3.y);
            ABSACC(acc[2][0], rvc.x, lv0.x); ABSACC(acc[2][0], rvc.y, lv0.y);
            ABSACC(acc[2][1], rvc.x, lv1.x); ABSACC(acc[2][1], rvc.y, lv1.y);
            ABSACC(acc[2][2], rvc.x, lv2.x); ABSACC(acc[2][2], rvc.y, lv2.y);
            ABSACC(acc[2][3], rvc.x, lv3.x); ABSACC(acc[2][3], rvc.y, lv3.y);
            ABSACC(acc[3][0], rvd.x, lv0.x); ABSACC(acc[3][0], rvd.y, lv0.y);
            ABSACC(acc[3][1], rvd.x, lv1.x); ABSACC(acc[3][1], rvd.y, lv1.y);
            ABSACC(acc[3][2], rvd.x, lv2.x); ABSACC(acc[3][2], rvd.y, lv2.y);
            ABSACC(acc[3][3], rvd.x, lv3.x); ABSACC(acc[3][3], rvd.y, lv3.y);
        }
    }

    // ---- epilogue: fold packed halves -> dist matrix in smem ----
    __syncthreads();   // everyone done reading rowS
    float* db = reinterpret_cast<float*>(rowS);   // [16][256] floats
    #pragma unroll
    for (int ri = 0; ri < 4; ++ri) {
        float* drow = db + (r0 + ri) * LATS_CTA;
        #pragma unroll
        for (int j = 0; j < 4; ++j) {
            float lo = __uint_as_float((unsigned)(acc[ri][j] & 0xffffffffULL));
            float hi = __uint_as_float((unsigned)(acc[ri][j] >> 32));
            drow[c0 + 64 * j] = lo + hi;
        }
    }
    __syncthreads();

    // stage-1 reduce: thread -> row tid>>4, 16-float segment (tid&15), staggered
    {
        int row = tid >> 4;
        int seg = (tid & 15) * 16;
        const float* p = db + row * LATS_CTA;
        float m0 = 1e30f, m1 = 1e30f, m2 = 1e30f, m3 = 1e30f;
        #pragma unroll 8
        for (int q = 0; q < 16; ++q)
            ins4(p[seg + ((q + tid) & 15)], m0, m1, m2, m3);
        float4* c4 = reinterpret_cast<float4*>(latS);   // [16][16] float4
        c4[row * 16 + (tid & 15)] = make_float4(m0, m1, m2, m3);
    }
    __syncthreads();

    if (tid < ROWS_CTA) {
        const float* cf = reinterpret_cast<const float*>(latS) + tid * 64;
        float m0 = 1e30f, m1 = 1e30f, m2 = 1e30f, m3 = 1e30f;
        #pragma unroll 8
        for (int k = 0; k < 64; ++k)
            ins4(cf[(k + 4 * tid) & 63], m0, m1, m2, m3);
        float4* dst = reinterpret_cast<float4*>(
            g_cand + ((size_t)(rowBase + tid) * NLB + blockIdx.y) * 4);
        *dst = make_float4(m0, m1, m2, m3);
    }
}

// ---------------------------------------------------------------------------
__global__ void k2_merge_tail() {
    int idx = blockIdx.x * blockDim.x + threadIdx.x;
    if (idx >= M_ROWS) return;
    const float* p = g_cand + (size_t)idx * NLB * 4;
    float m0 = 1e30f, m1 = 1e30f, m2 = 1e30f, m3 = 1e30f;
    #pragma unroll 4
    for (int q = 0; q < NLB * 4; ++q) ins4(p[q], m0, m1, m2, m3);
    g_tail[idx] = (m0 + m1 + m2 + m3) * 0.25f;
}

// ---------------------------------------------------------------------------
// Kernel 3: exact top-64 threshold via 4-level radix select, then huber mean
// ---------------------------------------------------------------------------
__global__ void k3_top64_huber(float* __restrict__ out) {
    __shared__ int hist[256];
    __shared__ unsigned s_prefix;
    __shared__ int s_need;
    __shared__ float s_hs[8];
    __shared__ int s_c[8];

    const int t = threadIdx.x;

    unsigned b[8];
    #pragma unroll
    for (int k = 0; k < 8; ++k) b[k] = __float_as_uint(g_tail[t + 256 * k]);

    if (t == 0) { s_prefix = 0u; s_need = 64; }

    #pragma unroll
    for (int lvl = 0; lvl < 4; ++lvl) {
        const int shift = 24 - 8 * lvl;
        hist[t] = 0;
        __syncthreads();
        unsigned pfx = s_prefix;
        #pragma unroll
        for (int k = 0; k < 8; ++k) {
            bool match = (lvl == 0) || ((b[k] >> (shift + 8)) == pfx);
            if (match) atomicAdd(&hist[(b[k] >> shift) & 255], 1);
        }
        __syncthreads();
        if (t == 0) {
            int need = s_need, cum = 0, bin = 0;
            #pragma unroll 4
            for (int q = 255; q >= 0; --q) {
                int h = hist[q];
                if (cum + h >= need) { bin = q; s_need = need - cum; break; }
                cum += h;
            }
            s_prefix = (pfx << ((lvl == 0) ? 0 : 8)) | (unsigned)bin;
        }
        __syncthreads();
    }

    const unsigned T = s_prefix;   // bit pattern of the 64th-largest value

    int c = 0; float hs = 0.0f;
    #pragma unroll
    for (int k = 0; k < 8; ++k)
        if (b[k] > T) { ++c; hs += huber1(__uint_as_float(b[k])); }
    #pragma unroll
    for (int o = 16; o; o >>= 1) {
        c  += __shfl_xor_sync(0xffffffffu, c, o);
        hs += __shfl_xor_sync(0xffffffffu, hs, o);
    }
    if ((t & 31) == 0) { s_c[t >> 5] = c; s_hs[t >> 5] = hs; }
    __syncthreads();
    if (t == 0) {
        int ngt = 0; float tot = 0.0f;
        #pragma unroll
        for (int w = 0; w < 8; ++w) { ngt += s_c[w]; tot += s_hs[w]; }
        float tv = __uint_as_float(T);
        out[0] = (tot + (float)(64 - ngt) * huber1(tv)) * (1.0f / 64.0f);
    }
}

// ---------------------------------------------------------------------------
extern "C" void kernel_launch(void* const* d_in, const int* in_sizes, int n_in,
                              void* d_out, int out_size) {
    const float* a = (const float*)d_in[0];
    const float* b = (const float*)d_in[1];
    const float *space, *lats;
    if (in_sizes[0] == M_ROWS * DIM) { space = a; lats = b; }
    else                             { space = b; lats = a; }

    cudaFuncSetAttribute(k1_cdist_min4,
                         cudaFuncAttributeMaxDynamicSharedMemorySize, K1_SMEM);

    k0_transpose<<<N_LAT / 32, 256>>>(lats);
    dim3 g1(NRB, NLB);   // 128 x 32
    k1_cdist_min4<<<g1, 256, K1_SMEM>>>(space);
    k2_merge_tail<<<(M_ROWS + 255) / 256, 256>>>();
    k3_top64_huber<<<1, 256>>>((float*)d_out);
}

// round 17
// speedup vs baseline: 1.0189x; 1.0189x over previous
#include <cuda_runtime.h>
#include <cuda_bf16.h>

// Fixed shapes
#define M_ROWS   2048
#define N_LAT    8192
#define DIM      256
#define ROWS_CTA 32
#define LATS_CTA 256
#define NRB      (M_ROWS / ROWS_CTA)   // 64
#define NLB      (N_LAT / LATS_CTA)    // 32
#define NQ_TOT   (DIM / 4)             // 64 quads
#define NSTAGE   8                     // stages of 32 floats (8 quads)
#define QPS      8
#define STAGE_BYTES (QPS * LATS_CTA * 16)   // 32KB

#define ROWS_BYTES (NQ_TOT * ROWS_CTA * 16)      // 32KB
#define LATS_BYTES (2 * QPS * LATS_CTA * 16)     // 64KB
#define K1_SMEM    (ROWS_BYTES + LATS_BYTES + 64)

typedef unsigned long long ull;

__device__ float4 g_latT[NQ_TOT * N_LAT];   // quad-major transposed latents (8MB)
__device__ float  g_cand[M_ROWS * NLB * 4];
__device__ float  g_tail[M_ROWS];

// A += |R + L|  (packed f32x2; R holds negated row values)
#define ABSACC(A, R, L) do { ull _d;                                \
    asm("add.rn.f32x2 %0, %1, %2;" : "=l"(_d) : "l"(R), "l"(L));    \
    _d &= 0x7fffffff7fffffffULL;                                    \
    asm("add.rn.f32x2 %0, %1, %2;" : "=l"(A) : "l"(A), "l"(_d));    \
} while (0)

#define MBAR_INIT(a, c) \
    asm volatile("mbarrier.init.shared.b64 [%0], %1;" :: "r"(a), "r"(c) : "memory")
#define MBAR_EXPECT(a, b) \
    asm volatile("mbarrier.arrive.expect_tx.shared.b64 _, [%0], %1;" :: "r"(a), "r"(b) : "memory")
#define BULK_G2S(dst, src, n, bar) \
    asm volatile("cp.async.bulk.shared::cluster.global.mbarrier::complete_tx::bytes [%0], [%1], %2, [%3];" \
                 :: "r"(dst), "l"(src), "r"(n), "r"(bar) : "memory")

static __device__ __forceinline__ void mbar_wait(unsigned bar, unsigned parity) {
    asm volatile(
        "{\n\t"
        ".reg .pred P;\n\t"
        "WAIT_%=:\n\t"
        "mbarrier.try_wait.parity.acquire.cta.shared::cta.b64 P, [%0], %1, 0x989680;\n\t"
        "@P bra.uni DONE_%=;\n\t"
        "bra.uni WAIT_%=;\n\t"
        "DONE_%=:\n\t"
        "}" :: "r"(bar), "r"(parity) : "memory");
}

static __device__ __forceinline__ void ins4(float v, float& m0, float& m1, float& m2, float& m3) {
    if (v < m3) {
        float c2 = fminf(v,  m2), d3 = fmaxf(v,  m2);
        float c1 = fminf(c2, m1), d2 = fmaxf(c2, m1);
        float c0 = fminf(c1, m0), d1 = fmaxf(c1, m0);
        m0 = c0; m1 = d1; m2 = d2; m3 = d3;
    }
}

static __device__ __forceinline__ float huber1(float x) {
    return (x < 1.0f) ? (0.5f * x * x) : (x - 0.5f);
}

// ---------------------------------------------------------------------------
// Kernel 0: transpose latents -> g_latT[quad][lat] (float4 of 4 consecutive d)
// ---------------------------------------------------------------------------
__global__ void k0_transpose(const float* __restrict__ lat) {
    __shared__ float4 sm[32][65];   // padded
    const int tid = threadIdx.x;
    const int lb = blockIdx.x * 32;
    #pragma unroll
    for (int k = 0; k < 8; ++k) {
        int idx = tid + k * 256;      // 2048 float4
        int r = idx >> 6, q = idx & 63;
        sm[r][q] = reinterpret_cast<const float4*>(lat)[(size_t)(lb + r) * 64 + q];
    }
    __syncthreads();
    #pragma unroll
    for (int k = 0; k < 8; ++k) {
        int idx = tid + k * 256;
        int q = idx >> 5, l = idx & 31;
        g_latT[(size_t)q * N_LAT + lb + l] = sm[l][q];
    }
}

// ---------------------------------------------------------------------------
// Kernel 1: L1 cdist 32-row x 256-latent tile; min-4 per (row, latblock)
// grid (64, 32), block 256, 2 CTAs/SM, 96KB dynamic smem.
// Double-buffered bulk-copy staging, one mbar_wait + syncthreads per stage.
// ---------------------------------------------------------------------------
__global__ void __launch_bounds__(256, 2)
k1_cdist_min4(const float* __restrict__ space) {
    extern __shared__ char smem[];
    float4* rowS = reinterpret_cast<float4*>(smem);                 // [64][32]
    float4* latS = reinterpret_cast<float4*>(smem + ROWS_BYTES);    // [2][8][256]
    ull*    mbar = reinterpret_cast<ull*>(smem + ROWS_BYTES + LATS_BYTES);

    const int tid = threadIdx.x;
    const int rowBase = blockIdx.x * ROWS_CTA;
    const int latBase = blockIdx.y * LATS_CTA;
    const int r0 = (tid >> 6) * 8;     // warp-uniform: 0,8,16,24
    const int c0 = tid & 63;           // lats c0, c0+64, c0+128, c0+192

    const unsigned bar0 = (unsigned)__cvta_generic_to_shared(&mbar[0]);
    const unsigned bar1 = (unsigned)__cvta_generic_to_shared(&mbar[1]);

    if (tid == 0) { MBAR_INIT(bar0, 1); MBAR_INIT(bar1, 1); }

    // ---- stage rows negated: unit u -> row u&31, quad u>>5 (conflict-free) ----
    #pragma unroll
    for (int k = 0; k < 8; ++k) {
        int u = tid + k * 256;
        int r = u & 31, q = u >> 5;
        float4 v = reinterpret_cast<const float4*>(space + (size_t)(rowBase + r) * DIM)[q];
        rowS[q * ROWS_CTA + r] = make_float4(-v.x, -v.y, -v.z, -v.w);
    }
    __syncthreads();   // mbar init + rowS visible

    // prologue: stage 0 -> buf 0
    if (tid == 0) {
        MBAR_EXPECT(bar0, STAGE_BYTES);
        unsigned d = (unsigned)__cvta_generic_to_shared(&latS[0]);
        #pragma unroll
        for (int j = 0; j < QPS; ++j)
            BULK_G2S(d + j * LATS_CTA * 16,
                     (const char*)(g_latT + (size_t)j * N_LAT + latBase),
                     LATS_CTA * 16, bar0);
    }

    ull acc[8][4];
    #pragma unroll
    for (int i = 0; i < 8; ++i)
        #pragma unroll
        for (int j = 0; j < 4; ++j) acc[i][j] = 0ULL;

    for (int s = 0; s < NSTAGE; ++s) {
        mbar_wait((s & 1) ? bar1 : bar0, (s >> 1) & 1);
        __syncthreads();   // all threads passed wait => done reading buf[(s+1)&1]

        if (s + 1 < NSTAGE && tid == 0) {
            unsigned nb = ((s + 1) & 1) ? bar1 : bar0;
            MBAR_EXPECT(nb, STAGE_BYTES);
            unsigned d = (unsigned)__cvta_generic_to_shared(&latS[(size_t)((s + 1) & 1) * QPS * LATS_CTA]);
            #pragma unroll
            for (int j = 0; j < QPS; ++j)
                BULK_G2S(d + j * LATS_CTA * 16,
                         (const char*)(g_latT + (size_t)(QPS * (s + 1) + j) * N_LAT + latBase),
                         LATS_CTA * 16, nb);
        }

        #pragma unroll
        for (int q = 0; q < QPS; ++q) {
            const float4* lb = latS + ((size_t)(s & 1) * QPS + q) * LATS_CTA;
            ulonglong2 lv0 = *reinterpret_cast<const ulonglong2*>(lb + c0);
            ulonglong2 lv1 = *reinterpret_cast<const ulonglong2*>(lb + c0 + 64);
            ulonglong2 lv2 = *reinterpret_cast<const ulonglong2*>(lb + c0 + 128);
            ulonglong2 lv3 = *reinterpret_cast<const ulonglong2*>(lb + c0 + 192);
            const float4* rb = rowS + (QPS * s + q) * ROWS_CTA + r0;
            #pragma unroll
            for (int ri = 0; ri < 8; ++ri) {
                ulonglong2 rv = *reinterpret_cast<const ulonglong2*>(rb + ri);
                ABSACC(acc[ri][0], rv.x, lv0.x); ABSACC(acc[ri][0], rv.y, lv0.y);
                ABSACC(acc[ri][1], rv.x, lv1.x); ABSACC(acc[ri][1], rv.y, lv1.y);
                ABSACC(acc[ri][2], rv.x, lv2.x); ABSACC(acc[ri][2], rv.y, lv2.y);
                ABSACC(acc[ri][3], rv.x, lv3.x); ABSACC(acc[ri][3], rv.y, lv3.y);
            }
        }
    }

    // ---- epilogue: fold packed halves -> dist matrix in smem ----
    __syncthreads();   // everyone done reading rowS
    float* db = reinterpret_cast<float*>(rowS);   // [32][256] floats
    #pragma unroll
    for (int ri = 0; ri < 8; ++ri) {
        float* drow = db + (r0 + ri) * LATS_CTA;
        #pragma unroll
        for (int j = 0; j < 4; ++j) {
            float lo = __uint_as_float((unsigned)(acc[ri][j] & 0xffffffffULL));
            float hi = __uint_as_float((unsigned)(acc[ri][j] >> 32));
            drow[c0 + 64 * j] = lo + hi;
        }
    }
    __syncthreads();

    // stage-1 reduce: thread -> row tid>>3, 32-float segment (tid&7), staggered
    {
        int row = tid >> 3;
        int seg = (tid & 7) * 32;
        const float* p = db + row * LATS_CTA;
        float m0 = 1e30f, m1 = 1e30f, m2 = 1e30f, m3 = 1e30f;
        #pragma unroll 8
        for (int q = 0; q < 32; ++q)
            ins4(p[seg + ((q + tid) & 31)], m0, m1, m2, m3);
        float4* c4 = reinterpret_cast<float4*>(latS);   // [32][8] float4
        c4[row * 8 + (tid & 7)] = make_float4(m0, m1, m2, m3);
    }
    __syncthreads();

    if (tid < ROWS_CTA) {
        const float* cf = reinterpret_cast<const float*>(latS) + tid * 32;
        float m0 = 1e30f, m1 = 1e30f, m2 = 1e30f, m3 = 1e30f;
        #pragma unroll 8
        for (int k = 0; k < 32; ++k)
            ins4(cf[(k + tid) & 31], m0, m1, m2, m3);
        float4* dst = reinterpret_cast<float4*>(
            g_cand + ((size_t)(rowBase + tid) * NLB + blockIdx.y) * 4);
        *dst = make_float4(m0, m1, m2, m3);
    }
}

// ---------------------------------------------------------------------------
__global__ void k2_merge_tail() {
    int idx = blockIdx.x * blockDim.x + threadIdx.x;
    if (idx >= M_ROWS) return;
    const float* p = g_cand + (size_t)idx * NLB * 4;
    float m0 = 1e30f, m1 = 1e30f, m2 = 1e30f, m3 = 1e30f;
    #pragma unroll 4
    for (int q = 0; q < NLB * 4; ++q) ins4(p[q], m0, m1, m2, m3);
    g_tail[idx] = (m0 + m1 + m2 + m3) * 0.25f;
}

// ---------------------------------------------------------------------------
// Kernel 3: exact top-64 threshold via 4-level radix select (8-bit digits on
// the positive-float bit pattern, order-monotone), then huber mean.
// ---------------------------------------------------------------------------
__global__ void k3_top64_huber(float* __restrict__ out) {
    __shared__ int hist[256];
    __shared__ unsigned s_prefix;
    __shared__ int s_need;
    __shared__ float s_hs[8];
    __shared__ int s_c[8];

    const int t = threadIdx.x;

    unsigned b[8];
    #pragma unroll
    for (int k = 0; k < 8; ++k) b[k] = __float_as_uint(g_tail[t + 256 * k]);

    if (t == 0) { s_prefix = 0u; s_need = 64; }

    #pragma unroll
    for (int lvl = 0; lvl < 4; ++lvl) {
        const int shift = 24 - 8 * lvl;
        hist[t] = 0;
        __syncthreads();
        unsigned pfx = s_prefix;
        #pragma unroll
        for (int k = 0; k < 8; ++k) {
            bool match = (lvl == 0) || ((b[k] >> (shift + 8)) == pfx);
            if (match) atomicAdd(&hist[(b[k] >> shift) & 255], 1);
        }
        __syncthreads();
        if (t == 0) {
            int need = s_need, cum = 0, bin = 0;
            #pragma unroll 4
            for (int q = 255; q >= 0; --q) {
                int h = hist[q];
                if (cum + h >= need) { bin = q; s_need = need - cum; break; }
                cum += h;
            }
            s_prefix = (pfx << ((lvl == 0) ? 0 : 8)) | (unsigned)bin;
        }
        __syncthreads();
    }

    const unsigned T = s_prefix;   // bit pattern of the 64th-largest value

    int c = 0; float hs = 0.0f;
    #pragma unroll
    for (int k = 0; k < 8; ++k)
        if (b[k] > T) { ++c; hs += huber1(__uint_as_float(b[k])); }
    #pragma unroll
    for (int o = 16; o; o >>= 1) {
        c  += __shfl_xor_sync(0xffffffffu, c, o);
        hs += __shfl_xor_sync(0xffffffffu, hs, o);
    }
    if ((t & 31) == 0) { s_c[t >> 5] = c; s_hs[t >> 5] = hs; }
    __syncthreads();
    if (t == 0) {
        int ngt = 0; float tot = 0.0f;
        #pragma unroll
        for (int w = 0; w < 8; ++w) { ngt += s_c[w]; tot += s_hs[w]; }
        float tv = __uint_as_float(T);
        out[0] = (tot + (float)(64 - ngt) * huber1(tv)) * (1.0f / 64.0f);
    }
}

// ---------------------------------------------------------------------------
extern "C" void kernel_launch(void* const* d_in, const int* in_sizes, int n_in,
                              void* d_out, int out_size) {
    const float* a = (const float*)d_in[0];
    const float* b = (const float*)d_in[1];
    const float *space, *lats;
    if (in_sizes[0] == M_ROWS * DIM) { space = a; lats = b; }
    else                             { space = b; lats = a; }

    cudaFuncSetAttribute(k1_cdist_min4,
                         cudaFuncAttributeMaxDynamicSharedMemorySize, K1_SMEM);

    k0_transpose<<<N_LAT / 32, 256>>>(lats);
    dim3 g1(NRB, NLB);   // 64 x 32
    k1_cdist_min4<<<g1, 256, K1_SMEM>>>(space);
    k2_merge_tail<<<(M_ROWS + 255) / 256, 256>>>();
    k3_top64_huber<<<1, 256>>>((float*)d_out);
}